// round 1
// baseline (speedup 1.0000x reference)
#include <cuda_runtime.h>
#include <math.h>

#define NBOX 4096
#define NT   1024
#define EPT  (NBOX / NT)   // 4 elements per thread

// Shared-memory resident state for the whole SoftNMS scan.
struct SmemState {
    float  s[NBOX];        // masked scores: -INF == inactive
    float4 box[NBOX];      // x1,y1,x2,y2
    float  area[NBOX];
    int    lab[NBOX];
    float  rv[32];         // cross-warp argmax scratch
    int    ri[32];
    float  selx1, sely1, selx2, sely2, selarea;
    int    sellab;
    int    done;
};

extern __shared__ char smem_raw[];

__global__ __launch_bounds__(NT, 1)
void softnms_kernel(const float* __restrict__ g_boxes,
                    const float* __restrict__ g_scores,
                    const int*   __restrict__ g_labels,
                    float*       __restrict__ g_out)
{
    SmemState* sm = reinterpret_cast<SmemState*>(smem_raw);
    const int tid = threadIdx.x;
    const int wid = tid >> 5;
    const int lid = tid & 31;

    // ---- load everything to SMEM ----
#pragma unroll
    for (int k = 0; k < EPT; k++) {
        int j = tid + k * NT;
        float4 b = reinterpret_cast<const float4*>(g_boxes)[j];
        sm->box[j]  = b;
        sm->area[j] = (b.z - b.x) * (b.w - b.y);
        sm->s[j]    = g_scores[j];
        sm->lab[j]  = g_labels[j];
    }
    if (tid == 0) sm->done = 0;
    __syncthreads();

    float* outBoxes  = g_out;                 // [N,4]
    float* outScores = g_out + 4 * NBOX;      // [N]
    float* outLabels = g_out + 5 * NBOX;      // [N] (float; -1 padding)

    int t;
    for (t = 0; t < NBOX; t++) {
        // ---- phase 1: argmax over masked scores (first-max tie-break) ----
        float bv = -INFINITY;
        int   bi = 0;
#pragma unroll
        for (int k = 0; k < EPT; k++) {
            int j = tid + k * NT;
            float v = sm->s[j];
            if (v > bv) { bv = v; bi = j; }   // strict >, ascending j => lowest idx kept
        }
#pragma unroll
        for (int o = 16; o > 0; o >>= 1) {
            float ov = __shfl_xor_sync(0xFFFFFFFFu, bv, o);
            int   oi = __shfl_xor_sync(0xFFFFFFFFu, bi, o);
            if (ov > bv || (ov == bv && oi < bi)) { bv = ov; bi = oi; }
        }
        if (lid == 0) { sm->rv[wid] = bv; sm->ri[wid] = bi; }
        __syncthreads();

        if (wid == 0) {
            bv = sm->rv[lid];
            bi = sm->ri[lid];
#pragma unroll
            for (int o = 16; o > 0; o >>= 1) {
                float ov = __shfl_xor_sync(0xFFFFFFFFu, bv, o);
                int   oi = __shfl_xor_sync(0xFFFFFFFFu, bi, o);
                if (ov > bv || (ov == bv && oi < bi)) { bv = ov; bi = oi; }
            }
            if (lid == 0) {
                if (bv == -INFINITY) {
                    sm->done = 1;             // no active boxes: freeze, fill later
                } else {
                    float4 b = sm->box[bi];
                    reinterpret_cast<float4*>(outBoxes)[t] = b;
                    outScores[t] = bv;                       // score BEFORE decay
                    outLabels[t] = (float)sm->lab[bi];
                    sm->selx1 = b.x;  sm->sely1 = b.y;
                    sm->selx2 = b.z;  sm->sely2 = b.w;
                    sm->selarea = sm->area[bi];
                    sm->sellab  = sm->lab[bi];
                    sm->s[bi] = -INFINITY;                   // deactivate selected
                }
            }
        }
        __syncthreads();

        if (sm->done) break;

        // ---- phase 2: decay same-class active boxes ----
        const float x1 = sm->selx1, y1 = sm->sely1;
        const float x2 = sm->selx2, y2 = sm->sely2;
        const float a1 = sm->selarea;
        const int   sl = sm->sellab;
#pragma unroll
        for (int k = 0; k < EPT; k++) {
            int j = tid + k * NT;
            float v = sm->s[j];
            if (v != -INFINITY && sm->lab[j] == sl) {
                float4 b = sm->box[j];
                float lx = fmaxf(x1, b.x);
                float ly = fmaxf(y1, b.y);
                float rx = fminf(x2, b.z);
                float ry = fminf(y2, b.w);
                float w  = fmaxf(rx - lx, 0.0f);
                float h  = fmaxf(ry - ly, 0.0f);
                float inter = w * h;
                float iou = inter / ((a1 + sm->area[j]) - inter + 1e-8f);
                float d   = expf(-(iou * iou) * 2.0f);     // sigma=0.5 -> *2
                float nv  = v * d;
                sm->s[j] = (nv >= 0.001f) ? nv : -INFINITY;
            }
        }
        __syncthreads();   // scores must be updated before next argmax
    }

    // ---- fill remaining (invalid) slots: zero boxes/scores, -1 labels ----
    for (int r = t + tid; r < NBOX; r += NT) {
        reinterpret_cast<float4*>(outBoxes)[r] = make_float4(0.f, 0.f, 0.f, 0.f);
        outScores[r] = 0.0f;
        outLabels[r] = -1.0f;
    }
}

extern "C" void kernel_launch(void* const* d_in, const int* in_sizes, int n_in,
                              void* d_out, int out_size)
{
    const float* boxes  = (const float*)d_in[0];
    const float* scores = (const float*)d_in[1];
    const int*   labels = (const int*)d_in[2];
    float*       out    = (float*)d_out;

    size_t smem = sizeof(SmemState);
    cudaFuncSetAttribute(softnms_kernel,
                         cudaFuncAttributeMaxDynamicSharedMemorySize, (int)smem);
    softnms_kernel<<<1, NT, smem>>>(boxes, scores, labels, out);
}

// round 2
// speedup vs baseline: 3.1741x; 3.1741x over previous
#include <cuda_runtime.h>
#include <math.h>

#define NBOX 4096
#define NT   1024
#define NW   (NT / 32)       // 32 warps
#define EPT  (NBOX / NT)     // 4 elements per thread

// Shared memory: read-only box/label tables for the broadcast lookup of the
// selected box, plus double-buffered warp-argmax partials.
struct Smem {
    float4   sbox[NBOX];          // 64 KB
    int      slab[NBOX];          // 16 KB
    unsigned rv[2][NW];           // warp partial max keys (double-buffered)
    int      ri[2][NW];           // warp partial argmax indices
};

extern __shared__ char smem_raw[];

__global__ __launch_bounds__(NT, 1)
void softnms_kernel(const float* __restrict__ g_boxes,
                    const float* __restrict__ g_scores,
                    const int*   __restrict__ g_labels,
                    float*       __restrict__ g_out)
{
    Smem* sm = reinterpret_cast<Smem*>(smem_raw);
    const int tid = threadIdx.x;
    const int wid = tid >> 5;
    const int lid = tid & 31;

    // Per-thread register-resident state for the EPT owned boxes.
    float  sc[EPT];                              // score; -INF == inactive
    float  bx[EPT], by[EPT], bz[EPT], bw[EPT];   // box corners
    float  ar[EPT];                              // area
    int    lb[EPT];                              // label

#pragma unroll
    for (int k = 0; k < EPT; k++) {
        int j = tid + k * NT;
        float4 b = reinterpret_cast<const float4*>(g_boxes)[j];
        bx[k] = b.x; by[k] = b.y; bz[k] = b.z; bw[k] = b.w;
        ar[k] = (b.z - b.x) * (b.w - b.y);
        sc[k] = g_scores[j];
        lb[k] = g_labels[j];
        sm->sbox[j] = b;
        sm->slab[j] = lb[k];
    }
    __syncthreads();

    float* outBoxes  = g_out;             // [N,4]
    float* outScores = g_out + 4 * NBOX;  // [N]
    float* outLabels = g_out + 5 * NBOX;  // [N] float; -1 padding

    int t;
    for (t = 0; t < NBOX; t++) {
        const int buf = t & 1;

        // ---- local argmax over owned registers (lowest index on ties) ----
        unsigned bk = 0u;   // positive-float bits; 0 == inactive
        int      bi = 0x7fffffff;
#pragma unroll
        for (int k = 0; k < EPT; k++) {
            unsigned kk = __float_as_uint(fmaxf(sc[k], 0.0f)); // -INF -> 0
            if (kk > bk) { bk = kk; bi = tid + k * NT; }
        }

        // ---- warp argmax via redux (max key, then min index among winners) ----
        unsigned wm = __reduce_max_sync(0xFFFFFFFFu, bk);
        int cand = (bk == wm) ? bi : 0x7fffffff;
        int wi = __reduce_min_sync(0xFFFFFFFFu, cand);
        if (lid == 0) { sm->rv[buf][wid] = wm; sm->ri[buf][wid] = wi; }
        __syncthreads();    // the ONLY barrier in the loop

        // ---- every warp redundantly reduces the 32 partials: all threads
        //      learn (M, SI) with no second barrier / broadcast ----
        unsigned pk = sm->rv[buf][lid];
        int      pi = sm->ri[buf][lid];
        unsigned M = __reduce_max_sync(0xFFFFFFFFu, pk);
        if (M == 0u) break;                        // nothing active, uniform exit
        int c2 = (pk == M) ? pi : 0x7fffffff;
        int SI = __reduce_min_sync(0xFFFFFFFFu, c2);

        // Selected box: broadcast LDS (same address across the warp).
        float4 sb = sm->sbox[SI];
        int    sl = sm->slab[SI];
        float  a1 = (sb.z - sb.x) * (sb.w - sb.y);

        if (tid == 0) {
            reinterpret_cast<float4*>(outBoxes)[t] = sb;
            outScores[t] = __uint_as_float(M);     // score BEFORE decay
            outLabels[t] = (float)sl;
        }

        // ---- decay own elements (registers only) ----
#pragma unroll
        for (int k = 0; k < EPT; k++) {
            int j = tid + k * NT;
            if (j == SI) { sc[k] = -INFINITY; continue; }    // deactivate sel
            float v = sc[k];
            if (v != -INFINITY && lb[k] == sl) {
                float w = fminf(sb.z, bz[k]) - fmaxf(sb.x, bx[k]);
                float h = fminf(sb.w, bw[k]) - fmaxf(sb.y, by[k]);
                if (w > 0.0f && h > 0.0f) {                  // overlap is rare
                    float inter = w * h;
                    float iou = inter / ((a1 + ar[k]) - inter + 1e-8f);
                    float d   = expf(-(iou * iou) * 2.0f);   // sigma=0.5 -> *2
                    float nv  = v * d;
                    sc[k] = (nv >= 0.001f) ? nv : -INFINITY;
                }
            }
        }
        // no barrier needed: decay touched only this thread's registers;
        // rv/ri are double-buffered across iterations.
    }

    // ---- fill remaining (invalid) slots ----
    for (int r = t + tid; r < NBOX; r += NT) {
        reinterpret_cast<float4*>(outBoxes)[r] = make_float4(0.f, 0.f, 0.f, 0.f);
        outScores[r] = 0.0f;
        outLabels[r] = -1.0f;
    }
}

extern "C" void kernel_launch(void* const* d_in, const int* in_sizes, int n_in,
                              void* d_out, int out_size)
{
    const float* boxes  = (const float*)d_in[0];
    const float* scores = (const float*)d_in[1];
    const int*   labels = (const int*)d_in[2];
    float*       out    = (float*)d_out;

    size_t smem = sizeof(Smem);
    cudaFuncSetAttribute(softnms_kernel,
                         cudaFuncAttributeMaxDynamicSharedMemorySize, (int)smem);
    softnms_kernel<<<1, NT, smem>>>(boxes, scores, labels, out);
}